// round 13
// baseline (speedup 1.0000x reference)
#include <cuda_runtime.h>
#include <cuda_fp16.h>
#include <cstdint>

// ---------------------------------------------------------------------------
// Seq2Seq RNN (tanh), B=1024, T=128, H=512, L=4, PRED_LEN=10.
// Round 13: single persistent dataflow encoder with layer-interleaved CTA->SM
// mapping (l = bid & 3; CLC packs consecutive bids on adjacent SMs, so each
// layer spreads over all SMs). Decoder: single dataflow launch (R11/R12).
// Split-fp16 GEMM: f32-accum main product + f16-accum corrections (lo planes
// pre-scaled 2^11). fp32 state in global, rel_err ~3e-6.
// ---------------------------------------------------------------------------

#define ACT_L 67108864LL  // halves per (layer, hi/lo) activation plane
#define LO_SCALE 2048.0f
#define LO_INV   4.8828125e-4f

static __device__ __half g_act[8LL * ACT_L];   // [4 layers][2 hi/lo][b*t][512]
static __device__ __half g_wenc_hi[2097152];   // [4][512 n][1024 k] (k = Wih|Whh)
static __device__ __half g_wenc_lo[2097152];   // lo scaled by 2^11
static __device__ __half g_wdec_hi[2097152];
static __device__ __half g_wdec_lo[2097152];
static __device__ __half g_dh_hi[4194304];     // [2][4][1024][512]
static __device__ __half g_dh_lo[4194304];
static __device__ float  g_decout[5242880];    // [1024][10][512]
static __device__ int    g_cnt_enc[4 * 128 * 16];  // [l][t][m] -> 8 when done
static __device__ int    g_cnt_dec[40 * 32];       // [step][m] -> 16 when done

// Encoder smem: 2 stages x 4 planes (Ah, Al, Bh, Bl) x 64 rows x 40-half pitch
#define ESTAGE_H   10240
#define ESMEM_BYTES (2 * ESTAGE_H * 2)   // 40960 bytes
#define EPL_AH 0
#define EPL_AL 2560
#define EPL_BH 5120
#define EPL_BL 7680

// Decoder smem: 2 stages x 4 planes x 32 rows x 40-half pitch
#define DSTAGE_H   5120
#define DSMEM_BYTES (2 * DSTAGE_H * 2)   // 20480 bytes
#define DPL_AH 0
#define DPL_AL 1280
#define DPL_BH 2560
#define DPL_BL 3840

__device__ __forceinline__ uint32_t smem_u32(const void* p) {
    return (uint32_t)__cvta_generic_to_shared(p);
}

__device__ __forceinline__ void cp16(uint32_t saddr, const void* g) {
    asm volatile("cp.async.cg.shared.global [%0], [%1], 16;\n" :: "r"(saddr), "l"(g));
}

// f32-accumulator mma (main product)
__device__ __forceinline__ void mma16816(float* c,
                                         uint32_t a0, uint32_t a1, uint32_t a2, uint32_t a3,
                                         uint32_t b0, uint32_t b1) {
    asm volatile(
        "mma.sync.aligned.m16n8k16.row.col.f32.f16.f16.f32 "
        "{%0,%1,%2,%3}, {%4,%5,%6,%7}, {%8,%9}, {%0,%1,%2,%3};"
        : "+f"(c[0]), "+f"(c[1]), "+f"(c[2]), "+f"(c[3])
        : "r"(a0), "r"(a1), "r"(a2), "r"(a3), "r"(b0), "r"(b1));
}

// f16-accumulator mma (correction products)
__device__ __forceinline__ void mma16816h(uint32_t* c,
                                          uint32_t a0, uint32_t a1, uint32_t a2, uint32_t a3,
                                          uint32_t b0, uint32_t b1) {
    asm volatile(
        "mma.sync.aligned.m16n8k16.row.col.f16.f16.f16.f16 "
        "{%0,%1}, {%2,%3,%4,%5}, {%6,%7}, {%0,%1};"
        : "+r"(c[0]), "+r"(c[1])
        : "r"(a0), "r"(a1), "r"(a2), "r"(a3), "r"(b0), "r"(b1));
}

__device__ __forceinline__ void ldsm_x4(uint32_t addr, uint32_t& r0, uint32_t& r1,
                                        uint32_t& r2, uint32_t& r3) {
    asm volatile("ldmatrix.sync.aligned.m8n8.x4.shared.b16 {%0,%1,%2,%3}, [%4];"
                 : "=r"(r0), "=r"(r1), "=r"(r2), "=r"(r3) : "r"(addr));
}

__device__ __forceinline__ int ld_acquire(const int* p) {
    int v;
    asm volatile("ld.acquire.gpu.b32 %0, [%1];" : "=r"(v) : "l"(p));
    return v;
}

__device__ __forceinline__ void wait_cnt(const int* p, int target) {
    int iter = 0;
    while (ld_acquire(p) < target) {
        __nanosleep(64);
        if (++iter > (1 << 22)) break;
    }
}

__device__ __forceinline__ float corr_extract(uint32_t packed, int j) {
    const __half2 h2 = *reinterpret_cast<const __half2*>(&packed);
    return j ? __high2float(h2) : __low2float(h2);
}

// ---------------------------------------------------------------------------
// Encoder step core: 64x64 tile, 256 threads (4 warps M x 2 warps N).
// out = tanh(X@Wih^T + H@Whh^T + bih + bhh). Weight k in [0,512) = X part,
// [512,1024) = H part. W layout [n][k], ld 1024. Lo planes scaled 2^11.
// ---------------------------------------------------------------------------
__device__ __forceinline__ void enc_step_core(
    __half* sm, int bm0, int bn0,
    const __half* __restrict__ Xhi, const __half* __restrict__ Xlo, long long ldx,
    const __half* __restrict__ Hhi, const __half* __restrict__ Hlo, long long ldh,
    const __half* __restrict__ Whi, const __half* __restrict__ Wlo,
    const float* __restrict__ bih, const float* __restrict__ bhh,
    __half* __restrict__ outHi, __half* __restrict__ outLo, long long ldoh,
    float* __restrict__ out32, long long ldo32,
    int kstart, int kend,
    const float* __restrict__ Xraw, long long ldxraw, const float* __restrict__ Wih0)
{
    const int tid = threadIdx.x;
    const int lane = tid & 31;
    const int warp = tid >> 5;
    const int wm = (warp & 3) * 16;
    const int wn = (warp >> 2) * 32;

    float acc[2][2][4];
    uint32_t accC[2][2][2];
#pragma unroll
    for (int a = 0; a < 2; ++a)
#pragma unroll
        for (int b = 0; b < 2; ++b) {
#pragma unroll
            for (int q = 0; q < 4; ++q) acc[a][b][q] = 0.f;
            accC[a][b][0] = 0u;
            accC[a][b][1] = 0u;
        }

    if (Xraw) {  // layer-0 input projection (K=6), direct fp32
        float xr[2][6];
#pragma unroll
        for (int i = 0; i < 2; ++i) {
            const int m = bm0 + wm + (lane >> 2) + i * 8;
#pragma unroll
            for (int k = 0; k < 6; ++k) xr[i][k] = Xraw[(long long)m * ldxraw + k];
        }
#pragma unroll
        for (int bg = 0; bg < 2; ++bg)
#pragma unroll
            for (int h = 0; h < 2; ++h)
#pragma unroll
                for (int j = 0; j < 2; ++j) {
                    const int n = bn0 + wn + bg * 16 + h * 8 + (lane & 3) * 2 + j;
#pragma unroll
                    for (int k = 0; k < 6; ++k) {
                        const float w = Wih0[n * 6 + k];
                        acc[bg][h][0 + j] += xr[0][k] * w;
                        acc[bg][h][2 + j] += xr[1][k] * w;
                    }
                }
    }

    const int nkb = (kend - kstart) >> 5;
    const int srow = tid >> 2;
    const int scq = (tid & 3) * 8;

    auto issue = [&](int cb) {
        const int s = cb & 1;
        const int k0 = kstart + cb * 32;
        const __half *axh, *axl;
        long long la;
        int kloc;
        if (k0 < 512) { axh = Xhi; axl = Xlo; la = ldx; kloc = k0; }
        else          { axh = Hhi; axl = Hlo; la = ldh; kloc = k0 - 512; }
        __half* st = sm + s * ESTAGE_H;
        const long long ga = (long long)(bm0 + srow) * la + kloc + scq;
        cp16(smem_u32(st + EPL_AH + srow * 40 + scq), axh + ga);
        cp16(smem_u32(st + EPL_AL + srow * 40 + scq), axl + ga);
        const long long gb = (long long)(bn0 + srow) * 1024 + k0 + scq;
        cp16(smem_u32(st + EPL_BH + srow * 40 + scq), Whi + gb);
        cp16(smem_u32(st + EPL_BL + srow * 40 + scq), Wlo + gb);
        asm volatile("cp.async.commit_group;" ::: "memory");
    };

    if (nkb > 0) {
        issue(0);
        for (int kb = 0; kb < nkb; ++kb) {
            asm volatile("cp.async.wait_group 0;" ::: "memory");
            __syncthreads();
            if (kb + 1 < nkb) issue(kb + 1);
            const __half* st = sm + (kb & 1) * ESTAGE_H;
            const int lrow = lane & 15;
#pragma unroll
            for (int kk = 0; kk < 32; kk += 16) {
                const int lcol = kk + ((lane >> 4) << 3);
                uint32_t ah0, ah1, ah2, ah3, al0, al1, al2, al3;
                ldsm_x4(smem_u32(st + EPL_AH + (wm + lrow) * 40 + lcol),
                        ah0, ah1, ah2, ah3);
                ldsm_x4(smem_u32(st + EPL_AL + (wm + lrow) * 40 + lcol),
                        al0, al1, al2, al3);
#pragma unroll
                for (int bg = 0; bg < 2; ++bg) {
                    uint32_t bh0, bh1, bh2, bh3, bl0, bl1, bl2, bl3;
                    ldsm_x4(smem_u32(st + EPL_BH + (wn + bg * 16 + lrow) * 40 + lcol),
                            bh0, bh1, bh2, bh3);
                    ldsm_x4(smem_u32(st + EPL_BL + (wn + bg * 16 + lrow) * 40 + lcol),
                            bl0, bl1, bl2, bl3);
                    mma16816(acc[bg][0], ah0, ah1, ah2, ah3, bh0, bh2);
                    mma16816(acc[bg][1], ah0, ah1, ah2, ah3, bh1, bh3);
                    mma16816h(accC[bg][0], al0, al1, al2, al3, bh0, bh2);
                    mma16816h(accC[bg][1], al0, al1, al2, al3, bh1, bh3);
                    mma16816h(accC[bg][0], ah0, ah1, ah2, ah3, bl0, bl2);
                    mma16816h(accC[bg][1], ah0, ah1, ah2, ah3, bl1, bl3);
                }
            }
            __syncthreads();
        }
    }

    // epilogue: main + scaled corr + bias, tanh, split store (+ optional fp32)
#pragma unroll
    for (int bg = 0; bg < 2; ++bg)
#pragma unroll
        for (int h = 0; h < 2; ++h)
#pragma unroll
            for (int i = 0; i < 2; ++i)
#pragma unroll
                for (int j = 0; j < 2; ++j) {
                    const int m = bm0 + wm + (lane >> 2) + i * 8;
                    const int n = bn0 + wn + bg * 16 + h * 8 + (lane & 3) * 2 + j;
                    const float cf = corr_extract(accC[bg][h][i], j) * LO_INV;
                    const float v = tanhf(acc[bg][h][i * 2 + j] + cf + bih[n] + bhh[n]);
                    const __half hi = __float2half_rn(v);
                    const __half lo =
                        __float2half_rn((v - __half2float(hi)) * LO_SCALE);
                    outHi[(long long)m * ldoh + n] = hi;
                    outLo[(long long)m * ldoh + n] = lo;
                    if (out32) out32[(long long)m * ldo32 + n] = v;
                }
}

// ---------------------------------------------------------------------------
// Persistent dataflow encoder. CTA map: l = bid & 3 (layer-interleaved so CLC's
// contiguous bid->SM placement spreads every layer across all SMs),
// m = (bid >> 2) & 15, n = bid >> 6. Tile (l,t) waits on cnt[l-1][t][m]==8 and
// cnt[l][t-1][m]==8, then releases cnt[l][t][m].
// ---------------------------------------------------------------------------
__global__ void __launch_bounds__(256, 4) enc_df_kernel(
    const float* __restrict__ xraw, const float* __restrict__ Wih0,
    const float* __restrict__ ebih, const float* __restrict__ ebhh,
    float* __restrict__ enc_out)
{
    extern __shared__ __half sm[];
    const int bid = blockIdx.x;
    const int l = bid & 3;
    const int m = (bid >> 2) & 15;
    const int n = bid >> 6;
    const int bm0 = m * 64;
    const int bn0 = n * 64;

    const __half* Whi = g_wenc_hi + (long long)l * 524288;
    const __half* Wlo = g_wenc_lo + (long long)l * 524288;
    __half* actl_hi = g_act + ((long long)l * 2 + 0) * ACT_L;
    __half* actl_lo = g_act + ((long long)l * 2 + 1) * ACT_L;
    const __half* prev_hi = (l > 0) ? g_act + ((long long)(l - 1) * 2) * ACT_L : nullptr;
    const __half* prev_lo = (l > 0) ? prev_hi + ACT_L : nullptr;
    const float* bi = ebih + l * 512;
    const float* bh = ebhh + l * 512;

    for (int t = 0; t < 128; ++t) {
        if (threadIdx.x == 0) {
            if (l > 0) wait_cnt(&g_cnt_enc[((l - 1) * 128 + t) * 16 + m], 8);
            if (t > 0) wait_cnt(&g_cnt_enc[(l * 128 + (t - 1)) * 16 + m], 8);
        }
        __syncthreads();

        const __half *Xhi = nullptr, *Xlo = nullptr, *Hhi = nullptr, *Hlo = nullptr;
        long long ldx = 0;
        int kstart = 512, kend = 512;
        const float* Xr = nullptr;
        if (l == 0) {
            Xr = xraw + (long long)t * 6;
        } else {
            Xhi = prev_hi + (long long)t * 512;
            Xlo = prev_lo + (long long)t * 512;
            ldx = 65536;
            kstart = 0;
        }
        if (t > 0) {
            Hhi = actl_hi + (long long)(t - 1) * 512;
            Hlo = actl_lo + (long long)(t - 1) * 512;
            kend = 1024;
        }
        float* o32 = (l == 3) ? enc_out + (long long)t * 512 : nullptr;

        enc_step_core(sm, bm0, bn0, Xhi, Xlo, ldx, Hhi, Hlo, 65536,
                      Whi, Wlo, bi, bh,
                      actl_hi + (long long)t * 512, actl_lo + (long long)t * 512,
                      65536, o32, 65536, kstart, kend, Xr, 768, Wih0);

        __threadfence();
        __syncthreads();
        if (threadIdx.x == 0) {
            atomicAdd(&g_cnt_enc[(l * 128 + t) * 16 + m], 1);
        }
    }
}

// ---------------------------------------------------------------------------
// Decoder tile core: 32x32, 128 threads (2 warps M x 2 warps N), K=1024.
// ---------------------------------------------------------------------------
__device__ __forceinline__ void dec_tile_core(
    __half* sm, int bm0, int bn0,
    const __half* __restrict__ Xhi, const __half* __restrict__ Xlo, long long ldx,
    const __half* __restrict__ Hhi, const __half* __restrict__ Hlo, long long ldh,
    const __half* __restrict__ Whi, const __half* __restrict__ Wlo,
    const float* __restrict__ bih, const float* __restrict__ bhh,
    __half* __restrict__ outHi, __half* __restrict__ outLo,
    float* __restrict__ out32, long long ldo32)
{
    const int tid = threadIdx.x;
    const int lane = tid & 31;
    const int warp = tid >> 5;
    const int wm = (warp & 1) * 16;
    const int wn = (warp >> 1) * 16;

    float acc[2][4];
    uint32_t accC[2][2];
#pragma unroll
    for (int h = 0; h < 2; ++h) {
#pragma unroll
        for (int q = 0; q < 4; ++q) acc[h][q] = 0.f;
        accC[h][0] = 0u;
        accC[h][1] = 0u;
    }

    const int srow = tid >> 2;
    const int scq = (tid & 3) * 8;

    auto issue = [&](int cb) {
        const int s = cb & 1;
        const int k0 = cb * 32;
        const __half *axh, *axl;
        long long la;
        int kloc;
        if (k0 < 512) { axh = Xhi; axl = Xlo; la = ldx; kloc = k0; }
        else          { axh = Hhi; axl = Hlo; la = ldh; kloc = k0 - 512; }
        __half* st = sm + s * DSTAGE_H;
        const long long ga = (long long)(bm0 + srow) * la + kloc + scq;
        cp16(smem_u32(st + DPL_AH + srow * 40 + scq), axh + ga);
        cp16(smem_u32(st + DPL_AL + srow * 40 + scq), axl + ga);
        const long long gb = (long long)(bn0 + srow) * 1024 + k0 + scq;
        cp16(smem_u32(st + DPL_BH + srow * 40 + scq), Whi + gb);
        cp16(smem_u32(st + DPL_BL + srow * 40 + scq), Wlo + gb);
        asm volatile("cp.async.commit_group;" ::: "memory");
    };

    issue(0);
    for (int kb = 0; kb < 32; ++kb) {
        asm volatile("cp.async.wait_group 0;" ::: "memory");
        __syncthreads();
        if (kb + 1 < 32) issue(kb + 1);
        const __half* st = sm + (kb & 1) * DSTAGE_H;
        const int lrow = lane & 15;
#pragma unroll
        for (int kk = 0; kk < 32; kk += 16) {
            const int lcol = kk + ((lane >> 4) << 3);
            uint32_t ah0, ah1, ah2, ah3, al0, al1, al2, al3;
            uint32_t bh0, bh1, bh2, bh3, bl0, bl1, bl2, bl3;
            ldsm_x4(smem_u32(st + DPL_AH + (wm + lrow) * 40 + lcol), ah0, ah1, ah2, ah3);
            ldsm_x4(smem_u32(st + DPL_AL + (wm + lrow) * 40 + lcol), al0, al1, al2, al3);
            ldsm_x4(smem_u32(st + DPL_BH + (wn + lrow) * 40 + lcol), bh0, bh1, bh2, bh3);
            ldsm_x4(smem_u32(st + DPL_BL + (wn + lrow) * 40 + lcol), bl0, bl1, bl2, bl3);
            mma16816(acc[0], ah0, ah1, ah2, ah3, bh0, bh2);
            mma16816(acc[1], ah0, ah1, ah2, ah3, bh1, bh3);
            mma16816h(accC[0], al0, al1, al2, al3, bh0, bh2);
            mma16816h(accC[1], al0, al1, al2, al3, bh1, bh3);
            mma16816h(accC[0], ah0, ah1, ah2, ah3, bl0, bl2);
            mma16816h(accC[1], ah0, ah1, ah2, ah3, bl1, bl3);
        }
        __syncthreads();
    }

#pragma unroll
    for (int h = 0; h < 2; ++h)
#pragma unroll
        for (int i = 0; i < 2; ++i)
#pragma unroll
            for (int j = 0; j < 2; ++j) {
                const int m = bm0 + wm + (lane >> 2) + i * 8;
                const int n = bn0 + wn + h * 8 + (lane & 3) * 2 + j;
                const float cf = corr_extract(accC[h][i], j) * LO_INV;
                const float v = tanhf(acc[h][i * 2 + j] + cf + bih[n] + bhh[n]);
                const __half hi = __float2half_rn(v);
                const __half lo = __float2half_rn((v - __half2float(hi)) * LO_SCALE);
                outHi[(long long)m * 512 + n] = hi;
                outLo[(long long)m * 512 + n] = lo;
                if (out32) out32[(long long)m * ldo32 + n] = v;
            }
}

// ---------------------------------------------------------------------------
// Persistent dataflow decoder: CTA = (m, n) over 32x32 tiles, 512 CTAs.
// 40 steps (s,l) chained via cnt_dec[step][m]==16.
// ---------------------------------------------------------------------------
__global__ void __launch_bounds__(128, 8) dec_df_kernel(
    const float* __restrict__ dbih, const float* __restrict__ dbhh)
{
    extern __shared__ __half sm[];
    const int bid = blockIdx.x;
    const int n = bid & 15;
    const int m = bid >> 4;   // 0..31
    const int bm0 = m * 32;
    const int bn0 = n * 32;

    for (int step = 0; step < 40; ++step) {
        const int s = step >> 2;
        const int l = step & 3;
        const int wset = s & 1;
        const int rset = (s - 1) & 1;

        if (threadIdx.x == 0) {
            if (l > 0) wait_cnt(&g_cnt_dec[(step - 1) * 32 + m], 16);
            else if (s > 0) wait_cnt(&g_cnt_dec[((s - 1) * 4 + 3) * 32 + m], 16);
            if (s > 0) wait_cnt(&g_cnt_dec[((s - 1) * 4 + l) * 32 + m], 16);
        }
        __syncthreads();

        const __half *Xhi, *Xlo, *Hhi, *Hlo;
        long long ldx, ldh;
        if (l == 0) {
            if (s == 0) {
                Xhi = g_act + 6 * ACT_L + 127LL * 512;
                Xlo = g_act + 7 * ACT_L + 127LL * 512;
                ldx = 65536;
            } else {
                Xhi = g_dh_hi + ((long long)rset * 4 + 3) * 524288;
                Xlo = g_dh_lo + ((long long)rset * 4 + 3) * 524288;
                ldx = 512;
            }
        } else {
            Xhi = g_dh_hi + ((long long)wset * 4 + (l - 1)) * 524288;
            Xlo = g_dh_lo + ((long long)wset * 4 + (l - 1)) * 524288;
            ldx = 512;
        }
        if (s == 0) {
            Hhi = g_act + ((long long)l * 2 + 0) * ACT_L + 127LL * 512;
            Hlo = g_act + ((long long)l * 2 + 1) * ACT_L + 127LL * 512;
            ldh = 65536;
        } else {
            Hhi = g_dh_hi + ((long long)rset * 4 + l) * 524288;
            Hlo = g_dh_lo + ((long long)rset * 4 + l) * 524288;
            ldh = 512;
        }
        __half* oHi = g_dh_hi + ((long long)wset * 4 + l) * 524288;
        __half* oLo = g_dh_lo + ((long long)wset * 4 + l) * 524288;
        float* o32 = (l == 3) ? g_decout + (long long)s * 512 : nullptr;

        dec_tile_core(sm, bm0, bn0, Xhi, Xlo, ldx, Hhi, Hlo, ldh,
                      g_wdec_hi + (long long)l * 524288,
                      g_wdec_lo + (long long)l * 524288,
                      dbih + l * 512, dbhh + l * 512, oHi, oLo, o32, 5120);

        __threadfence();
        __syncthreads();
        if (threadIdx.x == 0) {
            atomicAdd(&g_cnt_dec[step * 32 + m], 1);
        }
    }
}

// Split all weights once into fp16 hi/lo (lo scaled 2^11), layout [l][n][k],
// k = [Wih|Whh]. Also zero both dataflow counter arrays (graph replays).
__global__ void __launch_bounds__(256) prep_kernel(
    const float* __restrict__ eWih, const float* __restrict__ eWhh,
    const float* __restrict__ dWih, const float* __restrict__ dWhh)
{
    const unsigned idx = blockIdx.x * 256 + threadIdx.x;
    if (idx < 4 * 128 * 16) g_cnt_enc[idx] = 0;
    if (idx < 40 * 32) g_cnt_dec[idx] = 0;

    const int model = idx >> 21;
    const unsigned j = idx & 0x1FFFFFu;
    const int l = j >> 19;
    const int n = (j >> 10) & 511;
    const int k = j & 1023;
    float v;
    if (!model) {
        if (k < 512) v = (l == 0) ? 0.f : eWih[((unsigned)(l - 1) * 512 + n) * 512 + k];
        else         v = eWhh[((unsigned)l * 512 + n) * 512 + (k - 512)];
    } else {
        if (k < 512) v = dWih[((unsigned)l * 512 + n) * 512 + k];
        else         v = dWhh[((unsigned)l * 512 + n) * 512 + (k - 512)];
    }
    const __half hi = __float2half_rn(v);
    const __half lo = __float2half_rn((v - __half2float(hi)) * LO_SCALE);
    if (!model) { g_wenc_hi[j] = hi; g_wenc_lo[j] = lo; }
    else        { g_wdec_hi[j] = hi; g_wdec_lo[j] = lo; }
}

// outputs[r, n] = decout[r, :] @ fcW[n, :] + fcb[n]
__global__ void __launch_bounds__(256) fc_kernel(
    const float* __restrict__ in, const float* __restrict__ W,
    const float* __restrict__ b, float* __restrict__ out)
{
    __shared__ float Ws[6 * 512];
    const int tid = threadIdx.x;
    for (int i = tid; i < 6 * 512; i += 256) Ws[i] = W[i];
    __syncthreads();

    const int warp = tid >> 5, lane = tid & 31;
    const int row = blockIdx.x * 8 + warp;
    float p[6] = {0.f, 0.f, 0.f, 0.f, 0.f, 0.f};
    for (int k = lane; k < 512; k += 32) {
        const float v = in[(long long)row * 512 + k];
#pragma unroll
        for (int n = 0; n < 6; ++n) p[n] += v * Ws[n * 512 + k];
    }
#pragma unroll
    for (int off = 16; off > 0; off >>= 1)
#pragma unroll
        for (int n = 0; n < 6; ++n)
            p[n] += __shfl_down_sync(0xffffffffu, p[n], off);
    if (lane == 0) {
#pragma unroll
        for (int n = 0; n < 6; ++n) out[(long long)row * 6 + n] = p[n] + b[n];
    }
}

extern "C" void kernel_launch(void* const* d_in, const int* in_sizes, int n_in,
                              void* d_out, int out_size) {
    const float* x     = (const float*)d_in[0];
    const float* eWih0 = (const float*)d_in[1];
    const float* eWih  = (const float*)d_in[2];
    const float* eWhh  = (const float*)d_in[3];
    const float* ebih  = (const float*)d_in[4];
    const float* ebhh  = (const float*)d_in[5];
    const float* dWih  = (const float*)d_in[6];
    const float* dWhh  = (const float*)d_in[7];
    const float* dbih  = (const float*)d_in[8];
    const float* dbhh  = (const float*)d_in[9];
    const float* fcW   = (const float*)d_in[10];
    const float* fcb   = (const float*)d_in[11];

    float* out = (float*)d_out;
    float* enc_out = out;               // [1024,128,512]
    float* outputs = out + 67108864LL;  // [1024,10,6]

    float* decout;
    cudaGetSymbolAddress((void**)&decout, g_decout);

    cudaFuncSetAttribute(enc_df_kernel,
                         cudaFuncAttributeMaxDynamicSharedMemorySize, ESMEM_BYTES);
    cudaFuncSetAttribute(dec_df_kernel,
                         cudaFuncAttributeMaxDynamicSharedMemorySize, DSMEM_BYTES);

    // 1) weight split (lo scaled) + counter reset
    prep_kernel<<<16384, 256>>>(eWih, eWhh, dWih, dWhh);

    // 2) dataflow encoder: one persistent launch, 512 CTAs, layer-interleaved
    enc_df_kernel<<<512, 256, ESMEM_BYTES>>>(x, eWih0, ebih, ebhh, enc_out);

    // 3) dataflow decoder: one persistent launch, 512 CTAs = (m, n)
    dec_df_kernel<<<512, 128, DSMEM_BYTES>>>(dbih, dbhh);

    // 4) FC head
    fc_kernel<<<1280, 256>>>(decout, fcW, fcb, outputs);
}

// round 15
// speedup vs baseline: 1.2621x; 1.2621x over previous
#include <cuda_runtime.h>
#include <cuda_fp16.h>
#include <cstdint>

// ---------------------------------------------------------------------------
// Seq2Seq RNN (tanh), B=1024, T=128, H=512, L=4, PRED_LEN=10.
// Round 15: R14 multi-stream pipelined encoder graph (measured median 7.69 ms)
// with per-call stream/event lifecycle so no device memory outlives the graph.
// One non-blocking stream per layer; cell (l,t) ordered by stream (t) + event
// (layer edge). Cores: split-fp16 GEMM, f32-accum main + f16-accum
// corrections (lo planes pre-scaled 2^11). Decoder: 40 serial launches.
// ---------------------------------------------------------------------------

#define ACT_L 67108864LL  // halves per (layer, hi/lo) activation plane
#define LO_SCALE 2048.0f
#define LO_INV   4.8828125e-4f

static __device__ __half g_act[8LL * ACT_L];   // [4 layers][2 hi/lo][b*t][512]
static __device__ __half g_wenc_hi[2097152];   // [4][512 n][1024 k] (k = Wih|Whh)
static __device__ __half g_wenc_lo[2097152];   // lo scaled by 2^11
static __device__ __half g_wdec_hi[2097152];
static __device__ __half g_wdec_lo[2097152];
static __device__ __half g_dh_hi[4194304];     // [2][4][1024][512]
static __device__ __half g_dh_lo[4194304];
static __device__ float  g_decout[5242880];    // [1024][10][512]

// smem: 2 stages x 4 planes (Ah, Al, Bh, Bl) x 64 rows x 40-half pitch
#define ESTAGE_H   10240
#define ESMEM_BYTES (2 * ESTAGE_H * 2)   // 40960 bytes
#define EPL_AH 0
#define EPL_AL 2560
#define EPL_BH 5120
#define EPL_BL 7680

__device__ __forceinline__ uint32_t smem_u32(const void* p) {
    return (uint32_t)__cvta_generic_to_shared(p);
}

__device__ __forceinline__ void cp16(uint32_t saddr, const void* g) {
    asm volatile("cp.async.cg.shared.global [%0], [%1], 16;\n" :: "r"(saddr), "l"(g));
}

// f32-accumulator mma (main product)
__device__ __forceinline__ void mma16816(float* c,
                                         uint32_t a0, uint32_t a1, uint32_t a2, uint32_t a3,
                                         uint32_t b0, uint32_t b1) {
    asm volatile(
        "mma.sync.aligned.m16n8k16.row.col.f32.f16.f16.f32 "
        "{%0,%1,%2,%3}, {%4,%5,%6,%7}, {%8,%9}, {%0,%1,%2,%3};"
        : "+f"(c[0]), "+f"(c[1]), "+f"(c[2]), "+f"(c[3])
        : "r"(a0), "r"(a1), "r"(a2), "r"(a3), "r"(b0), "r"(b1));
}

// f16-accumulator mma (correction products)
__device__ __forceinline__ void mma16816h(uint32_t* c,
                                          uint32_t a0, uint32_t a1, uint32_t a2, uint32_t a3,
                                          uint32_t b0, uint32_t b1) {
    asm volatile(
        "mma.sync.aligned.m16n8k16.row.col.f16.f16.f16.f16 "
        "{%0,%1}, {%2,%3,%4,%5}, {%6,%7}, {%0,%1};"
        : "+r"(c[0]), "+r"(c[1])
        : "r"(a0), "r"(a1), "r"(a2), "r"(a3), "r"(b0), "r"(b1));
}

__device__ __forceinline__ void ldsm_x4(uint32_t addr, uint32_t& r0, uint32_t& r1,
                                        uint32_t& r2, uint32_t& r3) {
    asm volatile("ldmatrix.sync.aligned.m8n8.x4.shared.b16 {%0,%1,%2,%3}, [%4];"
                 : "=r"(r0), "=r"(r1), "=r"(r2), "=r"(r3) : "r"(addr));
}

__device__ __forceinline__ float corr_extract(uint32_t packed, int j) {
    const __half2 h2 = *reinterpret_cast<const __half2*>(&packed);
    return j ? __high2float(h2) : __low2float(h2);
}

// ---------------------------------------------------------------------------
// Step core: 64x64 tile, 256 threads (4 warps M x 2 warps N).
// out = tanh(X@Wih^T + H@Whh^T + bih + bhh). Weight k in [0,512) = X part,
// [512,1024) = H part. W layout [n][k], ld 1024. Lo planes scaled 2^11.
// ---------------------------------------------------------------------------
__device__ __forceinline__ void step_core(
    __half* sm, int bm0, int bn0,
    const __half* __restrict__ Xhi, const __half* __restrict__ Xlo, long long ldx,
    const __half* __restrict__ Hhi, const __half* __restrict__ Hlo, long long ldh,
    const __half* __restrict__ Whi, const __half* __restrict__ Wlo,
    const float* __restrict__ bih, const float* __restrict__ bhh,
    __half* __restrict__ outHi, __half* __restrict__ outLo, long long ldoh,
    float* __restrict__ out32, long long ldo32,
    int kstart, int kend,
    const float* __restrict__ Xraw, long long ldxraw, const float* __restrict__ Wih0)
{
    const int tid = threadIdx.x;
    const int lane = tid & 31;
    const int warp = tid >> 5;
    const int wm = (warp & 3) * 16;
    const int wn = (warp >> 2) * 32;

    float acc[2][2][4];
    uint32_t accC[2][2][2];
#pragma unroll
    for (int a = 0; a < 2; ++a)
#pragma unroll
        for (int b = 0; b < 2; ++b) {
#pragma unroll
            for (int q = 0; q < 4; ++q) acc[a][b][q] = 0.f;
            accC[a][b][0] = 0u;
            accC[a][b][1] = 0u;
        }

    if (Xraw) {  // layer-0 input projection (K=6), direct fp32
        float xr[2][6];
#pragma unroll
        for (int i = 0; i < 2; ++i) {
            const int m = bm0 + wm + (lane >> 2) + i * 8;
#pragma unroll
            for (int k = 0; k < 6; ++k) xr[i][k] = Xraw[(long long)m * ldxraw + k];
        }
#pragma unroll
        for (int bg = 0; bg < 2; ++bg)
#pragma unroll
            for (int h = 0; h < 2; ++h)
#pragma unroll
                for (int j = 0; j < 2; ++j) {
                    const int n = bn0 + wn + bg * 16 + h * 8 + (lane & 3) * 2 + j;
#pragma unroll
                    for (int k = 0; k < 6; ++k) {
                        const float w = Wih0[n * 6 + k];
                        acc[bg][h][0 + j] += xr[0][k] * w;
                        acc[bg][h][2 + j] += xr[1][k] * w;
                    }
                }
    }

    const int nkb = (kend - kstart) >> 5;
    const int srow = tid >> 2;
    const int scq = (tid & 3) * 8;

    auto issue = [&](int cb) {
        const int s = cb & 1;
        const int k0 = kstart + cb * 32;
        const __half *axh, *axl;
        long long la;
        int kloc;
        if (k0 < 512) { axh = Xhi; axl = Xlo; la = ldx; kloc = k0; }
        else          { axh = Hhi; axl = Hlo; la = ldh; kloc = k0 - 512; }
        __half* st = sm + s * ESTAGE_H;
        const long long ga = (long long)(bm0 + srow) * la + kloc + scq;
        cp16(smem_u32(st + EPL_AH + srow * 40 + scq), axh + ga);
        cp16(smem_u32(st + EPL_AL + srow * 40 + scq), axl + ga);
        const long long gb = (long long)(bn0 + srow) * 1024 + k0 + scq;
        cp16(smem_u32(st + EPL_BH + srow * 40 + scq), Whi + gb);
        cp16(smem_u32(st + EPL_BL + srow * 40 + scq), Wlo + gb);
        asm volatile("cp.async.commit_group;" ::: "memory");
    };

    if (nkb > 0) {
        issue(0);
        for (int kb = 0; kb < nkb; ++kb) {
            asm volatile("cp.async.wait_group 0;" ::: "memory");
            __syncthreads();
            if (kb + 1 < nkb) issue(kb + 1);
            const __half* st = sm + (kb & 1) * ESTAGE_H;
            const int lrow = lane & 15;
#pragma unroll
            for (int kk = 0; kk < 32; kk += 16) {
                const int lcol = kk + ((lane >> 4) << 3);
                uint32_t ah0, ah1, ah2, ah3, al0, al1, al2, al3;
                ldsm_x4(smem_u32(st + EPL_AH + (wm + lrow) * 40 + lcol),
                        ah0, ah1, ah2, ah3);
                ldsm_x4(smem_u32(st + EPL_AL + (wm + lrow) * 40 + lcol),
                        al0, al1, al2, al3);
#pragma unroll
                for (int bg = 0; bg < 2; ++bg) {
                    uint32_t bh0, bh1, bh2, bh3, bl0, bl1, bl2, bl3;
                    ldsm_x4(smem_u32(st + EPL_BH + (wn + bg * 16 + lrow) * 40 + lcol),
                            bh0, bh1, bh2, bh3);
                    ldsm_x4(smem_u32(st + EPL_BL + (wn + bg * 16 + lrow) * 40 + lcol),
                            bl0, bl1, bl2, bl3);
                    mma16816(acc[bg][0], ah0, ah1, ah2, ah3, bh0, bh2);
                    mma16816(acc[bg][1], ah0, ah1, ah2, ah3, bh1, bh3);
                    mma16816h(accC[bg][0], al0, al1, al2, al3, bh0, bh2);
                    mma16816h(accC[bg][1], al0, al1, al2, al3, bh1, bh3);
                    mma16816h(accC[bg][0], ah0, ah1, ah2, ah3, bl0, bl2);
                    mma16816h(accC[bg][1], ah0, ah1, ah2, ah3, bl1, bl3);
                }
            }
            __syncthreads();
        }
    }

    // epilogue: main + scaled corr + bias, tanh, split store (+ optional fp32)
#pragma unroll
    for (int bg = 0; bg < 2; ++bg)
#pragma unroll
        for (int h = 0; h < 2; ++h)
#pragma unroll
            for (int i = 0; i < 2; ++i)
#pragma unroll
                for (int j = 0; j < 2; ++j) {
                    const int m = bm0 + wm + (lane >> 2) + i * 8;
                    const int n = bn0 + wn + bg * 16 + h * 8 + (lane & 3) * 2 + j;
                    const float cf = corr_extract(accC[bg][h][i], j) * LO_INV;
                    const float v = tanhf(acc[bg][h][i * 2 + j] + cf + bih[n] + bhh[n]);
                    const __half hi = __float2half_rn(v);
                    const __half lo =
                        __float2half_rn((v - __half2float(hi)) * LO_SCALE);
                    outHi[(long long)m * ldoh + n] = hi;
                    outLo[(long long)m * ldoh + n] = lo;
                    if (out32) out32[(long long)m * ldo32 + n] = v;
                }
}

// One encoder cell (l, t): grid (16, 8) of 64x64 tiles.
__global__ void __launch_bounds__(256, 4) enc_cell_kernel(
    int l, int t,
    const float* __restrict__ xraw, const float* __restrict__ Wih0,
    const float* __restrict__ ebih, const float* __restrict__ ebhh,
    float* __restrict__ enc_out)
{
    extern __shared__ __half sm[];
    const int bm0 = blockIdx.x * 64;
    const int bn0 = blockIdx.y * 64;

    const __half* Whi = g_wenc_hi + (long long)l * 524288;
    const __half* Wlo = g_wenc_lo + (long long)l * 524288;
    __half* actl_hi = g_act + ((long long)l * 2 + 0) * ACT_L;
    __half* actl_lo = g_act + ((long long)l * 2 + 1) * ACT_L;

    const __half *Xhi = nullptr, *Xlo = nullptr, *Hhi = nullptr, *Hlo = nullptr;
    long long ldx = 0;
    int kstart = 512, kend = 512;
    const float* Xr = nullptr;

    if (l == 0) {
        Xr = xraw + (long long)t * 6;
    } else {
        const __half* prev = g_act + ((long long)(l - 1) * 2) * ACT_L;
        Xhi = prev + (long long)t * 512;
        Xlo = prev + ACT_L + (long long)t * 512;
        ldx = 65536;
        kstart = 0;
    }
    if (t > 0) {
        Hhi = actl_hi + (long long)(t - 1) * 512;
        Hlo = actl_lo + (long long)(t - 1) * 512;
        kend = 1024;
    }
    float* o32 = (l == 3) ? enc_out + (long long)t * 512 : nullptr;

    step_core(sm, bm0, bn0, Xhi, Xlo, ldx, Hhi, Hlo, 65536,
              Whi, Wlo, ebih + l * 512, ebhh + l * 512,
              actl_hi + (long long)t * 512, actl_lo + (long long)t * 512,
              65536, o32, 65536, kstart, kend, Xr, 768, Wih0);
}

// Decoder step: grid (16, 8) of 64x64 tiles, K=1024.
__global__ void __launch_bounds__(256, 4) dec_step_kernel(
    const __half* __restrict__ Xhi, const __half* __restrict__ Xlo, long long ldx,
    const __half* __restrict__ Hhi, const __half* __restrict__ Hlo, long long ldh,
    const __half* __restrict__ Whi, const __half* __restrict__ Wlo,
    const float* __restrict__ bih, const float* __restrict__ bhh,
    __half* __restrict__ outHi, __half* __restrict__ outLo,
    float* __restrict__ out32, long long ldo32)
{
    extern __shared__ __half sm[];
    step_core(sm, blockIdx.x * 64, blockIdx.y * 64,
              Xhi, Xlo, ldx, Hhi, Hlo, ldh, Whi, Wlo, bih, bhh,
              outHi, outLo, 512, out32, ldo32, 0, 1024, nullptr, 0, nullptr);
}

// Split all weights once into fp16 hi/lo (lo scaled 2^11), layout [l][n][k],
// k = [Wih|Whh].
__global__ void __launch_bounds__(256) prep_kernel(
    const float* __restrict__ eWih, const float* __restrict__ eWhh,
    const float* __restrict__ dWih, const float* __restrict__ dWhh)
{
    const unsigned idx = blockIdx.x * 256 + threadIdx.x;
    const int model = idx >> 21;
    const unsigned j = idx & 0x1FFFFFu;
    const int l = j >> 19;
    const int n = (j >> 10) & 511;
    const int k = j & 1023;
    float v;
    if (!model) {
        if (k < 512) v = (l == 0) ? 0.f : eWih[((unsigned)(l - 1) * 512 + n) * 512 + k];
        else         v = eWhh[((unsigned)l * 512 + n) * 512 + (k - 512)];
    } else {
        if (k < 512) v = dWih[((unsigned)l * 512 + n) * 512 + k];
        else         v = dWhh[((unsigned)l * 512 + n) * 512 + (k - 512)];
    }
    const __half hi = __float2half_rn(v);
    const __half lo = __float2half_rn((v - __half2float(hi)) * LO_SCALE);
    if (!model) { g_wenc_hi[j] = hi; g_wenc_lo[j] = lo; }
    else        { g_wdec_hi[j] = hi; g_wdec_lo[j] = lo; }
}

// outputs[r, n] = decout[r, :] @ fcW[n, :] + fcb[n]
__global__ void __launch_bounds__(256) fc_kernel(
    const float* __restrict__ in, const float* __restrict__ W,
    const float* __restrict__ b, float* __restrict__ out)
{
    __shared__ float Ws[6 * 512];
    const int tid = threadIdx.x;
    for (int i = tid; i < 6 * 512; i += 256) Ws[i] = W[i];
    __syncthreads();

    const int warp = tid >> 5, lane = tid & 31;
    const int row = blockIdx.x * 8 + warp;
    float p[6] = {0.f, 0.f, 0.f, 0.f, 0.f, 0.f};
    for (int k = lane; k < 512; k += 32) {
        const float v = in[(long long)row * 512 + k];
#pragma unroll
        for (int n = 0; n < 6; ++n) p[n] += v * Ws[n * 512 + k];
    }
#pragma unroll
    for (int off = 16; off > 0; off >>= 1)
#pragma unroll
        for (int n = 0; n < 6; ++n)
            p[n] += __shfl_down_sync(0xffffffffu, p[n], off);
    if (lane == 0) {
#pragma unroll
        for (int n = 0; n < 6; ++n) out[(long long)row * 6 + n] = p[n] + b[n];
    }
}

extern "C" void kernel_launch(void* const* d_in, const int* in_sizes, int n_in,
                              void* d_out, int out_size) {
    const float* x     = (const float*)d_in[0];
    const float* eWih0 = (const float*)d_in[1];
    const float* eWih  = (const float*)d_in[2];
    const float* eWhh  = (const float*)d_in[3];
    const float* ebih  = (const float*)d_in[4];
    const float* ebhh  = (const float*)d_in[5];
    const float* dWih  = (const float*)d_in[6];
    const float* dWhh  = (const float*)d_in[7];
    const float* dbih  = (const float*)d_in[8];
    const float* dbhh  = (const float*)d_in[9];
    const float* fcW   = (const float*)d_in[10];
    const float* fcb   = (const float*)d_in[11];

    float* out = (float*)d_out;
    float* enc_out = out;               // [1024,128,512]
    float* outputs = out + 67108864LL;  // [1024,10,6]

    __half *actB, *dhHi, *dhLo, *wdHi, *wdLo;
    float* decout;
    cudaGetSymbolAddress((void**)&actB, g_act);
    cudaGetSymbolAddress((void**)&dhHi, g_dh_hi);
    cudaGetSymbolAddress((void**)&dhLo, g_dh_lo);
    cudaGetSymbolAddress((void**)&wdHi, g_wdec_hi);
    cudaGetSymbolAddress((void**)&wdLo, g_wdec_lo);
    cudaGetSymbolAddress((void**)&decout, g_decout);

    cudaFuncSetAttribute(enc_cell_kernel,
                         cudaFuncAttributeMaxDynamicSharedMemorySize, ESMEM_BYTES);
    cudaFuncSetAttribute(dec_step_kernel,
                         cudaFuncAttributeMaxDynamicSharedMemorySize, ESMEM_BYTES);

    // Per-call stream/event lifecycle: created here, destroyed before return
    // so no driver-side device memory outlives the captured graph.
    cudaStream_t sl[4];
    cudaEvent_t ev_cell[4][128];
    cudaEvent_t ev_fork;
    for (int l = 0; l < 4; ++l) {
        cudaStreamCreateWithFlags(&sl[l], cudaStreamNonBlocking);
        for (int t = 0; t < 128; ++t)
            cudaEventCreateWithFlags(&ev_cell[l][t], cudaEventDisableTiming);
    }
    cudaEventCreateWithFlags(&ev_fork, cudaEventDisableTiming);

    const dim3 grid(16, 8);

    // 1) weight split on the origin (capture) stream, then fork.
    prep_kernel<<<16384, 256>>>(eWih, eWhh, dWih, dWhh);
    cudaEventRecord(ev_fork, 0);
    for (int l = 0; l < 4; ++l) cudaStreamWaitEvent(sl[l], ev_fork, 0);

    // 2) pipelined encoder: stream per layer; cell (l,t) after (l,t-1) via
    //    stream order and after (l-1,t) via event.
    for (int t = 0; t < 128; ++t) {
        for (int l = 0; l < 4; ++l) {
            if (l > 0) cudaStreamWaitEvent(sl[l], ev_cell[l - 1][t], 0);
            enc_cell_kernel<<<grid, 256, ESMEM_BYTES, sl[l]>>>(
                l, t, x, eWih0, ebih, ebhh, enc_out);
            cudaEventRecord(ev_cell[l][t], sl[l]);
        }
    }

    // 3) join all layer tails back onto the origin stream.
    for (int l = 0; l < 4; ++l) cudaStreamWaitEvent(0, ev_cell[l][127], 0);

    // 4) decoder: 10 steps x 4 layers, serial on origin stream.
    for (int s = 0; s < 10; ++s) {
        const int wset = s & 1;
        const int rset = (s - 1) & 1;
        for (int l = 0; l < 4; ++l) {
            const __half *Xhi, *Xlo, *Hhi, *Hlo;
            long long ldx, ldh;
            if (l == 0) {
                if (s == 0) {
                    Xhi = actB + 6 * ACT_L + 127LL * 512;
                    Xlo = actB + 7 * ACT_L + 127LL * 512;
                    ldx = 65536;
                } else {
                    Xhi = dhHi + ((long long)rset * 4 + 3) * 524288;
                    Xlo = dhLo + ((long long)rset * 4 + 3) * 524288;
                    ldx = 512;
                }
            } else {
                Xhi = dhHi + ((long long)wset * 4 + (l - 1)) * 524288;
                Xlo = dhLo + ((long long)wset * 4 + (l - 1)) * 524288;
                ldx = 512;
            }
            if (s == 0) {
                Hhi = actB + ((long long)l * 2 + 0) * ACT_L + 127LL * 512;
                Hlo = actB + ((long long)l * 2 + 1) * ACT_L + 127LL * 512;
                ldh = 65536;
            } else {
                Hhi = dhHi + ((long long)rset * 4 + l) * 524288;
                Hlo = dhLo + ((long long)rset * 4 + l) * 524288;
                ldh = 512;
            }
            __half* oHi = dhHi + ((long long)wset * 4 + l) * 524288;
            __half* oLo = dhLo + ((long long)wset * 4 + l) * 524288;
            float* o32 = (l == 3) ? decout + (long long)s * 512 : nullptr;
            dec_step_kernel<<<grid, 256, ESMEM_BYTES>>>(
                Xhi, Xlo, ldx, Hhi, Hlo, ldh,
                wdHi + (long long)l * 524288, wdLo + (long long)l * 524288,
                dbih + l * 512, dbhh + l * 512, oHi, oLo, o32, 5120);
        }
    }

    // 5) FC head
    fc_kernel<<<1280, 256>>>(decout, fcW, fcb, outputs);

    // 6) release all per-call resources (destruction is deferred by the
    //    driver until pending/captured work no longer needs them).
    for (int l = 0; l < 4; ++l) {
        for (int t = 0; t < 128; ++t) cudaEventDestroy(ev_cell[l][t]);
        cudaStreamDestroy(sl[l]);
    }
    cudaEventDestroy(ev_fork);
}